// round 9
// baseline (speedup 1.0000x reference)
#include <cuda_runtime.h>
#include <stdint.h>

#define NUM_OBJ_CLS 151
#define NUM_REL_CLS 51

// ---------------------------------------------------------------------------
// Fused kernel.
// Section 1 (obj_dists): exact one-hot (softmax of +/-1000 fp32 logits
//   underflows to one-hot). Grid-stride over float4s of the [n_obj,151] block.
// Section 2 (rel_dists): warp handles 32 pairs = 1632 output floats =
//   exactly 51 warp-wide stride-1 iterations. Load index space == store
//   index space: lane reads chunk-float f = k*32+lane from table[b(j)+c]
//   (j = f/51 via constant-divisor mulhi -> iterations fully independent,
//   row base via shfl) and stores directly to out[chunk_base+f]. Both sides
//   are dense 128B wavefronts (chunk base 128B-aligned: 32*204 = 51*128).
// R9: launch_bounds (256,6) frees regs (was clamped to 32 @ 8 blocks),
//     unroll 9 for ~1.3x more loads in flight; persistent single-wave grid.
// ---------------------------------------------------------------------------
__global__ void __launch_bounds__(256, 6)
fused_kernel(const int* __restrict__ labels,
             const int2* __restrict__ pairs,
             const float* __restrict__ table,
             float* __restrict__ obj_out,
             float* __restrict__ rel_out,
             int n_obj, int n_pairs) {
    const int tid_global = blockIdx.x * blockDim.x + threadIdx.x;
    const int n_threads  = gridDim.x * blockDim.x;

    // ---- Section 1: one-hot. ----
    {
        const int n_floats = n_obj * NUM_OBJ_CLS;
        const int n_vec = n_floats >> 2;
        for (int i = tid_global; i < n_vec; i += n_threads) {
            int f0 = i * 4;
            float4 v;
            #pragma unroll
            for (int k = 0; k < 4; k++) {
                int f = f0 + k;
                int r = f / NUM_OBJ_CLS, c = f - r * NUM_OBJ_CLS;
                float val = (__ldg(&labels[r]) == c) ? 1.0f : 0.0f;
                if (k == 0) v.x = val; else if (k == 1) v.y = val;
                else if (k == 2) v.z = val; else v.w = val;
            }
            *(float4*)(obj_out + f0) = v;
        }
        if (tid_global == 0) {
            for (int f = n_vec * 4; f < n_floats; f++) {
                int r = f / NUM_OBJ_CLS, c = f - r * NUM_OBJ_CLS;
                obj_out[f] = (__ldg(&labels[r]) == c) ? 1.0f : 0.0f;
            }
        }
    }

    // ---- Section 2: rel gather. ----
    const int lane = threadIdx.x & 31;
    const int warp_id   = tid_global >> 5;
    const int num_warps = n_threads >> 5;
    const int n_chunks  = n_pairs >> 5;

    for (int chunk = warp_id; chunk < n_chunks; chunk += num_warps) {
        const int p0 = chunk << 5;

        // Per-lane index resolution: 32 independent pair->label->base chains.
        int2 pr = __ldg(&pairs[p0 + lane]);
        int h = __ldg(&labels[pr.x]);
        int t = __ldg(&labels[pr.y]);
        int base = (h * NUM_OBJ_CLS + t) * NUM_REL_CLS;

        float* __restrict__ dst = rel_out + (size_t)p0 * NUM_REL_CLS;

        // 51 independent iterations (j,c via constant-divisor mulhi).
        #pragma unroll 9
        for (int k = 0; k < NUM_REL_CLS; k++) {
            int f = k * 32 + lane;
            int j = f / NUM_REL_CLS;
            int c = f - j * NUM_REL_CLS;
            int b = __shfl_sync(0xffffffffu, base, j);
            float v = __ldg(table + b + c);
            __stcs(dst + f, v);
        }
    }

    // Leftover pairs (n_pairs % 32): absent for 2M pairs, kept for generality.
    if (warp_id == 0) {
        for (int p = n_chunks << 5; p < n_pairs; p++) {
            int2 pr = __ldg(&pairs[p]);
            int h = __ldg(&labels[pr.x]);
            int t = __ldg(&labels[pr.y]);
            int b = (h * NUM_OBJ_CLS + t) * NUM_REL_CLS;
            float* __restrict__ dstp = rel_out + (size_t)p * NUM_REL_CLS;
            if (lane < NUM_REL_CLS) dstp[lane] = __ldg(table + b + lane);
            if (lane < NUM_REL_CLS - 32) dstp[32 + lane] = __ldg(table + b + 32 + lane);
        }
    }
}

extern "C" void kernel_launch(void* const* d_in, const int* in_sizes, int n_in,
                              void* d_out, int out_size) {
    const int*   labels = (const int*)d_in[0];          // [N_OBJ] int32
    const int2*  pairs  = (const int2*)d_in[1];         // [N_PAIRS, 2] int32
    const float* table  = (const float*)d_in[2];        // [151,151,51] f32

    const int n_obj   = in_sizes[0];
    const int n_pairs = in_sizes[1] / 2;

    float* obj_out = (float*)d_out;                               // [n_obj, 151]
    float* rel_out = obj_out + (size_t)n_obj * NUM_OBJ_CLS;       // [n_pairs, 51]

    // Persistent single wave: 148 SMs x 6 resident blocks.
    fused_kernel<<<888, 256>>>(labels, pairs, table, obj_out, rel_out,
                               n_obj, n_pairs);
}

// round 10
// speedup vs baseline: 1.0499x; 1.0499x over previous
#include <cuda_runtime.h>
#include <stdint.h>

#define NUM_OBJ_CLS 151
#define NUM_REL_CLS 51

// ---------------------------------------------------------------------------
// Fused kernel (R8 config: launch_bounds(256,8), unroll 6, grid 2048).
// R10: software-pipelined chunk index resolution — the pair->label->label
// dependent chain (~2 x L2 latency) for chunk i+1 is overlapped with chunk
// i's 51-iteration copy loop: pairs prefetch before the loop, labels
// resolution between the two loop halves.
// Section 1 (obj_dists): exact one-hot (softmax of +/-1000 underflows).
// Section 2 (rel_dists): warp = 32 pairs = 1632 floats = 51 dense stride-1
// warp iterations; load index space == store index space (no staging);
// j = f/51 via constant mulhi so iterations are independent.
// ---------------------------------------------------------------------------
__global__ void __launch_bounds__(256, 8)
fused_kernel(const int* __restrict__ labels,
             const int2* __restrict__ pairs,
             const float* __restrict__ table,
             float* __restrict__ obj_out,
             float* __restrict__ rel_out,
             int n_obj, int n_pairs) {
    const int tid_global = blockIdx.x * blockDim.x + threadIdx.x;
    const int n_threads  = gridDim.x * blockDim.x;

    // ---- Section 1: one-hot. ----
    {
        const int n_floats = n_obj * NUM_OBJ_CLS;
        const int n_vec = n_floats >> 2;
        for (int i = tid_global; i < n_vec; i += n_threads) {
            int f0 = i * 4;
            float4 v;
            #pragma unroll
            for (int k = 0; k < 4; k++) {
                int f = f0 + k;
                int r = f / NUM_OBJ_CLS, c = f - r * NUM_OBJ_CLS;
                float val = (__ldg(&labels[r]) == c) ? 1.0f : 0.0f;
                if (k == 0) v.x = val; else if (k == 1) v.y = val;
                else if (k == 2) v.z = val; else v.w = val;
            }
            *(float4*)(obj_out + f0) = v;
        }
        if (tid_global == 0) {
            for (int f = n_vec * 4; f < n_floats; f++) {
                int r = f / NUM_OBJ_CLS, c = f - r * NUM_OBJ_CLS;
                obj_out[f] = (__ldg(&labels[r]) == c) ? 1.0f : 0.0f;
            }
        }
    }

    // ---- Section 2: rel gather, pipelined across chunks. ----
    const int lane = threadIdx.x & 31;
    const int warp_id   = tid_global >> 5;
    const int num_warps = n_threads >> 5;
    const int n_chunks  = n_pairs >> 5;

    int chunk = warp_id;
    int h = 0, t = 0;
    if (chunk < n_chunks) {
        int2 pr = __ldg(&pairs[(chunk << 5) + lane]);
        h = __ldg(&labels[pr.x]);
        t = __ldg(&labels[pr.y]);
    }

    while (chunk < n_chunks) {
        const int base = (h * NUM_OBJ_CLS + t) * NUM_REL_CLS;
        const int next = chunk + num_warps;

        // Prefetch next chunk's pair row now; it lands (~L2 latency)
        // well before the mid-loop labels resolution consumes it.
        int2 pr_n = make_int2(0, 0);
        if (next < n_chunks) pr_n = __ldg(&pairs[(next << 5) + lane]);

        float* __restrict__ dst = rel_out + (size_t)(chunk << 5) * NUM_REL_CLS;

        // First half of the copy loop: k = 0..23.
        #pragma unroll 6
        for (int k = 0; k < 24; k++) {
            int f = k * 32 + lane;
            int j = f / NUM_REL_CLS;           // constant-divisor mulhi
            int c = f - j * NUM_REL_CLS;
            int b = __shfl_sync(0xffffffffu, base, j);
            __stcs(dst + f, __ldg(table + b + c));
        }

        // Resolve next chunk's labels (pr_n has landed by now); the loads
        // overlap with the second half of the copy loop.
        if (next < n_chunks) {
            h = __ldg(&labels[pr_n.x]);
            t = __ldg(&labels[pr_n.y]);
        }

        // Second half: k = 24..50.
        #pragma unroll 6
        for (int k = 24; k < NUM_REL_CLS; k++) {
            int f = k * 32 + lane;
            int j = f / NUM_REL_CLS;
            int c = f - j * NUM_REL_CLS;
            int b = __shfl_sync(0xffffffffu, base, j);
            __stcs(dst + f, __ldg(table + b + c));
        }

        chunk = next;
    }

    // Leftover pairs (n_pairs % 32): absent for 2M pairs, kept for generality.
    if (warp_id == 0) {
        for (int p = n_chunks << 5; p < n_pairs; p++) {
            int2 pr = __ldg(&pairs[p]);
            int hh = __ldg(&labels[pr.x]);
            int tt = __ldg(&labels[pr.y]);
            int b = (hh * NUM_OBJ_CLS + tt) * NUM_REL_CLS;
            float* __restrict__ dstp = rel_out + (size_t)p * NUM_REL_CLS;
            if (lane < NUM_REL_CLS) dstp[lane] = __ldg(table + b + lane);
            if (lane < NUM_REL_CLS - 32) dstp[32 + lane] = __ldg(table + b + 32 + lane);
        }
    }
}

extern "C" void kernel_launch(void* const* d_in, const int* in_sizes, int n_in,
                              void* d_out, int out_size) {
    const int*   labels = (const int*)d_in[0];          // [N_OBJ] int32
    const int2*  pairs  = (const int2*)d_in[1];         // [N_PAIRS, 2] int32
    const float* table  = (const float*)d_in[2];        // [151,151,51] f32

    const int n_obj   = in_sizes[0];
    const int n_pairs = in_sizes[1] / 2;

    float* obj_out = (float*)d_out;                               // [n_obj, 151]
    float* rel_out = obj_out + (size_t)n_obj * NUM_OBJ_CLS;       // [n_pairs, 51]

    fused_kernel<<<2048, 256>>>(labels, pairs, table, obj_out, rel_out,
                                n_obj, n_pairs);
}